// round 8
// baseline (speedup 1.0000x reference)
#include <cuda_runtime.h>
#include <math.h>
#include <float.h>

#define Bq 64
#define Nq 16384
#define Mq 64
#define Cq 256
#define GAMMAq 0.95f
#define EPSq 1e-16f
#define NOUT 66      // M + 2
#define SCH 64       // streaming chunks per batch (256 rows each)

// ---------------- scratch (static device globals; no allocation) ----------------
__device__ float g_k[Bq * Mq];
__device__ float g_beta[Bq];
__device__ float g_gate[Bq];
__device__ float g_E[(size_t)Bq * Nq];           // exp(beta*(sim-1))
__device__ float g_psum[Bq * SCH];               // per-chunk partial sums of E
__device__ unsigned long long g_cand[Bq * 16];   // 4 chunks x 4 candidate keys
__device__ int g_ticket[Bq];                     // K3 last-block tickets (reset by K3)
__device__ int g_ready[Bq];                      // proj-done flags (reset by K3)

// ---------------- kernel 2: proj (producer blocks) + fused streaming pass -------
// grid: (SCH+1, Bq), block 512.
// blockIdx.x == 0  : producer — computes proj for batch b, sets g_ready[b], exits.
//                    Lowest linear id in its batch => scheduled before consumers.
// blockIdx.x >= 1  : streaming chunk (256 rows), spins on g_ready[b] (wave-1 only).
__global__ void __launch_bounds__(512)
ntm_stream_kernel(const float* __restrict__ memory,
                  const float* __restrict__ w_prev,
                  const float* __restrict__ emb,
                  const float* __restrict__ W,
                  const float* __restrict__ bias,
                  float* __restrict__ out) {
    const int b = blockIdx.y;
    const int tid = threadIdx.x;
    const int lane = tid & 31;

    // ---------- producer block: projection ----------
    if (blockIdx.x == 0) {
        __shared__ float sh_o[NOUT];
        const int warp = tid >> 5;  // 0..15
        const float* __restrict__ e = emb + (size_t)b * Cq;
        for (int o = warp; o < NOUT; o += 16) {
            const float* __restrict__ wrow = W + (size_t)o * Cq;
            float acc = 0.0f;
#pragma unroll
            for (int i = 0; i < 8; i++) {
                const int c = lane + 32 * i;
                acc = fmaf(__ldg(&e[c]), __ldg(&wrow[c]), acc);
            }
#pragma unroll
            for (int s = 16; s > 0; s >>= 1)
                acc += __shfl_xor_sync(0xffffffffu, acc, s);
            if (lane == 0) sh_o[o] = acc + bias[o];
        }
        __syncthreads();
        if (tid < Mq) g_k[b * Mq + tid] = sh_o[tid];
        if (tid == 0) {
            const float ob = sh_o[Mq];
            g_beta[b] = (ob > 20.0f) ? ob : log1pf(expf(ob));
            const float og = sh_o[Mq + 1];
            g_gate[b] = 1.0f / (1.0f + expf(-og));
        }
        __threadfence();
        __syncthreads();
        if (tid == 0) g_ready[b] = 1;   // release
        return;
    }

    // ---------- streaming block ----------
    const int n0 = (blockIdx.x - 1) * 256;
    const int hw = tid >> 4;   // 0..31
    const int l16 = tid & 15;

    __shared__ float4 sh_k4[16];
    __shared__ float sh_ww[256];
    __shared__ float sh_E[256];
    __shared__ float s_knorm;

    // acquire proj results (spin only while producer is still running)
    if (tid == 0) {
        volatile int* rf = g_ready;
        while (rf[b] == 0) __nanosleep(64);
    }
    __syncthreads();
    __threadfence();

    const float gv = g_gate[b];
    const float beta = g_beta[b];

    float kn = 0.0f;
    if (tid < 16) {
        const float4 k4 = ((const float4*)(g_k + (size_t)b * Mq))[tid];
        sh_k4[tid] = k4;
        kn = k4.x * k4.x + k4.y * k4.y + k4.z * k4.z + k4.w * k4.w;
    }
    if (tid < 32) {
#pragma unroll
        for (int s = 8; s > 0; s >>= 1)
            kn += __shfl_xor_sync(0xffffffffu, kn, s);
        if (tid == 0) s_knorm = sqrtf(kn);
    }
    if (tid < 256) {
        const int n = n0 + tid;
        const float wrp  = w_prev[((size_t)b * 3 + 1) * Nq + n];
        const float wlup = w_prev[((size_t)b * 3 + 2) * Nq + n];
        sh_ww[tid] = gv * wrp + (1.0f - gv) * wlup;
    }
    __syncthreads();

    const float knorm = s_knorm;
    const float4 kv = sh_k4[l16];
    float* __restrict__ newmem = out + (size_t)Bq * 3 * Nq;
    const float4* __restrict__ mem4 = (const float4*)memory;
    float4* __restrict__ out4 = (float4*)newmem;

    const size_t base = ((size_t)b * Nq + n0 + hw) * (Mq / 4) + l16;

    // Phase A: batch all 8 loads (long read burst)
    float4 m[8];
#pragma unroll
    for (int r = 0; r < 8; r++)
        m[r] = __ldcs(&mem4[base + (size_t)r * 32 * (Mq / 4)]);

    // Phase B: all 8 stores (long write burst, independent of shuffle chains)
#pragma unroll
    for (int r = 0; r < 8; r++) {
        const float ww = sh_ww[hw + 32 * r];
        float4 o4;
        o4.x = m[r].x + ww * kv.x;
        o4.y = m[r].y + ww * kv.y;
        o4.z = m[r].z + ww * kv.z;
        o4.w = m[r].w + ww * kv.w;
        __stcs(&out4[base + (size_t)r * 32 * (Mq / 4)], o4);
    }

    // Phase C: reductions -> E = exp(beta*(sim-1))
#pragma unroll
    for (int r = 0; r < 8; r++) {
        float dot = m[r].x * kv.x + m[r].y * kv.y + m[r].z * kv.z + m[r].w * kv.w;
        float nrm = m[r].x * m[r].x + m[r].y * m[r].y + m[r].z * m[r].z + m[r].w * m[r].w;
#pragma unroll
        for (int s = 8; s > 0; s >>= 1) {
            dot += __shfl_xor_sync(0xffffffffu, dot, s);
            nrm += __shfl_xor_sync(0xffffffffu, nrm, s);
        }
        if (l16 == 0) {
            const float sim = dot / (knorm * sqrtf(nrm) + EPSq);
            sh_E[hw + 32 * r] = expf(beta * (sim - 1.0f));
        }
    }
    __syncthreads();

    if (tid < 32) {
        const float4 e0 = ((const float4*)sh_E)[tid];
        const float4 e1 = ((const float4*)sh_E)[tid + 32];
        ((float4*)(g_E + (size_t)b * Nq + n0))[tid] = e0;
        ((float4*)(g_E + (size_t)b * Nq + n0))[tid + 32] = e1;
        float ps = e0.x + e0.y + e0.z + e0.w + e1.x + e1.y + e1.z + e1.w;
#pragma unroll
        for (int s = 16; s > 0; s >>= 1)
            ps += __shfl_xor_sync(0xffffffffu, ps, s);
        if (tid == 0) g_psum[b * SCH + (blockIdx.x - 1)] = ps;
    }
}

// ---------------- kernel 3: elementwise + per-chunk top-4 + last-block merge ----
// grid: 256 blocks (4 per batch), 1024 threads, 4 elems/thread.
__global__ void __launch_bounds__(1024, 1)
ntm_elem_kernel(const float* __restrict__ w_prev, float* __restrict__ out) {
    const int blk = blockIdx.x;
    const int b = blk >> 2;
    const int c = blk & 3;
    const int tid = threadIdx.x;
    const int warp = tid >> 5;
    const int lane = tid & 31;
    const int nbase = c * 4096;

    __shared__ float s_inv;
    __shared__ unsigned long long sh_keys[128];
    __shared__ int s_last;

    // reduce the 64 partial sums (deterministic fixed order)
    if (tid < 32) {
        const float* __restrict__ ps = g_psum + b * SCH;
        float v = ps[tid] + ps[tid + 32];
#pragma unroll
        for (int s = 16; s > 0; s >>= 1)
            v += __shfl_xor_sync(0xffffffffu, v, s);
        if (tid == 0) s_inv = 1.0f / v;
    }
    __syncthreads();
    const float inv = s_inv;
    const float gv = g_gate[b];

    const float* __restrict__ Ep   = g_E + (size_t)b * Nq;
    const float* __restrict__ wup  = w_prev + (size_t)b * 3 * Nq;
    const float* __restrict__ wrp  = wup + Nq;
    const float* __restrict__ wlup = wup + 2 * Nq;
    float* __restrict__ w_u_out  = out + (size_t)b * 3 * Nq;
    float* __restrict__ w_r_out  = w_u_out + Nq;
    float* __restrict__ w_lu_out = w_u_out + 2 * Nq;

    unsigned long long tk[4] = {~0ULL, ~0ULL, ~0ULL, ~0ULL};

#pragma unroll
    for (int j = 0; j < 4; j++) {
        const int n = nbase + j * 1024 + tid;
        const float wr = Ep[n] * inv;
        const float ww = gv * wrp[n] + (1.0f - gv) * wlup[n];
        const float wu = GAMMAq * wup[n] + wr + ww;
        w_r_out[n] = wr;
        w_u_out[n] = wu;
        w_lu_out[n] = 0.0f;

        const unsigned long long key =
            ((unsigned long long)__float_as_uint(wu) << 32) | (unsigned int)n;
        if (key < tk[3]) {
            tk[3] = key;
#pragma unroll
            for (int q = 3; q > 0; q--) {
                if (tk[q] < tk[q - 1]) {
                    unsigned long long t = tk[q]; tk[q] = tk[q - 1]; tk[q - 1] = t;
                }
            }
        }
    }

    // per-warp top-4 via 4 rounds of shfl argmin + pop (no barriers)
#pragma unroll
    for (int round = 0; round < 4; round++) {
        unsigned long long v = tk[0];
#pragma unroll
        for (int s = 16; s > 0; s >>= 1) {
            const unsigned long long o = __shfl_xor_sync(0xffffffffu, v, s);
            if (o < v) v = o;
        }
        if (tk[0] == v) {  // unique key -> exactly one popper
            tk[0] = tk[1]; tk[1] = tk[2]; tk[2] = tk[3]; tk[3] = ~0ULL;
        }
        if (lane == 0) sh_keys[warp * 4 + round] = v;
    }
    __syncthreads();

    // warp 0: reduce 128 candidates -> this chunk's top-4 -> g_cand
    if (warp == 0) {
        unsigned long long bk[4] = {~0ULL, ~0ULL, ~0ULL, ~0ULL};
#pragma unroll
        for (int j = 0; j < 4; j++) {
            const unsigned long long key = sh_keys[lane + 32 * j];
            if (key < bk[3]) {
                bk[3] = key;
#pragma unroll
                for (int q = 3; q > 0; q--) {
                    if (bk[q] < bk[q - 1]) {
                        unsigned long long t = bk[q]; bk[q] = bk[q - 1]; bk[q - 1] = t;
                    }
                }
            }
        }
#pragma unroll
        for (int round = 0; round < 4; round++) {
            unsigned long long v = bk[0];
#pragma unroll
            for (int s = 16; s > 0; s >>= 1) {
                const unsigned long long o = __shfl_xor_sync(0xffffffffu, v, s);
                if (o < v) v = o;
            }
            if (bk[0] == v) {
                bk[0] = bk[1]; bk[1] = bk[2]; bk[2] = bk[3]; bk[3] = ~0ULL;
            }
            if (lane == round) g_cand[(b * 4 + c) * 4 + round] = v;
        }
    }
    __syncthreads();

    // ticket: last block of this batch merges + scatters + resets flags
    if (tid == 0) {
        __threadfence();
        s_last = (atomicAdd(&g_ticket[b], 1) == 3);
    }
    __syncthreads();

    if (s_last && warp == 0) {
        unsigned long long key = (lane < 16) ? g_cand[b * 16 + lane] : ~0ULL;
#pragma unroll
        for (int round = 0; round < 4; round++) {
            unsigned long long v = key;
#pragma unroll
            for (int s = 16; s > 0; s >>= 1) {
                const unsigned long long o = __shfl_xor_sync(0xffffffffu, v, s);
                if (o < v) v = o;
            }
            if (key == v) key = ~0ULL;  // pop winner
            if (lane == round)
                w_lu_out[(int)(unsigned int)(v & 0xffffffffu)] = 1.0f;
        }
        if (lane == 0) {            // reset for next replay (stream-ordered)
            g_ticket[b] = 0;
            g_ready[b] = 0;
        }
    }
}

// ---------------- launch ----------------
extern "C" void kernel_launch(void* const* d_in, const int* in_sizes, int n_in,
                              void* d_out, int out_size) {
    const float* emb    = (const float*)d_in[0];  // (64, 256)
    const float* w_prev = (const float*)d_in[1];  // (64, 3, 16384)
    const float* memory = (const float*)d_in[2];  // (64, 16384, 64)
    const float* W      = (const float*)d_in[3];  // (66, 256)
    const float* bias   = (const float*)d_in[4];  // (66,)
    float* out = (float*)d_out;  // [w (64*3*16384) | new_memory (64*16384*64)]

    dim3 grid2(SCH + 1, Bq);
    ntm_stream_kernel<<<grid2, 512>>>(memory, w_prev, emb, W, bias, out);

    ntm_elem_kernel<<<Bq * 4, 1024>>>(w_prev, out);
}

// round 9
// speedup vs baseline: 1.5089x; 1.5089x over previous
#include <cuda_runtime.h>
#include <math.h>
#include <float.h>

#define Bq 64
#define Nq 16384
#define Mq 64
#define Cq 256
#define GAMMAq 0.95f
#define EPSq 1e-16f
#define NOUT 66     // M + 2
#define CHUNKS 128  // K2 grid.x = Nq/128

// ---------------- scratch (static device globals; no allocation) ----------------
__device__ float g_k[Bq * Mq];
__device__ float g_beta[Bq];
__device__ float g_gate[Bq];
__device__ float g_E[(size_t)Bq * Nq];           // exp(beta*(sim-1))
__device__ float g_psum[Bq * CHUNKS];            // per-K2-block partial sums of E
__device__ unsigned long long g_cand[Bq * 16];   // 4 chunks x 4 candidate keys
__device__ int g_ticket[Bq];                     // last-block-done tickets

// ---------------- kernel 1: projection, warp per (batch, output) ----------------
// Also resets the per-batch tickets for this call (ordered before K3's use via PDL sync chain).
__global__ void ntm_proj_kernel(const float* __restrict__ emb,
                                const float* __restrict__ W,
                                const float* __restrict__ bias) {
    if (blockIdx.x == 0 && threadIdx.x < Bq) g_ticket[threadIdx.x] = 0;

    const int wglob = (blockIdx.x * blockDim.x + threadIdx.x) >> 5;
    const int lane = threadIdx.x & 31;
    if (wglob >= Bq * NOUT) return;
    const int b = wglob / NOUT;
    const int o = wglob - b * NOUT;

    const float* __restrict__ e = emb + (size_t)b * Cq;
    const float* __restrict__ w = W + (size_t)o * Cq;

    float acc = 0.0f;
#pragma unroll
    for (int i = 0; i < 8; i++) {
        const int c = lane + 32 * i;
        acc = fmaf(__ldg(&e[c]), __ldg(&w[c]), acc);
    }
#pragma unroll
    for (int s = 16; s > 0; s >>= 1)
        acc += __shfl_xor_sync(0xffffffffu, acc, s);

    if (lane == 0) {
        acc += bias[o];
        if (o < Mq) {
            g_k[b * Mq + o] = acc;
        } else if (o == Mq) {
            g_beta[b] = (acc > 20.0f) ? acc : log1pf(expf(acc));
        } else {
            g_gate[b] = 1.0f / (1.0f + expf(-acc));
        }
    }
}

// ---------------- kernel 2: fused sim/exp + new_memory streaming pass -----------
// grid: (CHUNKS, Bq), block 512. Phase A/B/C structure (proven 6.2 TB/s).
// PDL: pure-input loads (memory rows, w_prev staging) issue BEFORE
// cudaGridDependencySynchronize(); proj outputs are read after.
__global__ void __launch_bounds__(512)
ntm_stream_kernel(const float* __restrict__ memory,
                  const float* __restrict__ w_prev,
                  float* __restrict__ out) {
    const int b = blockIdx.y;
    const int n0 = blockIdx.x * 128;
    const int tid = threadIdx.x;
    const int hw = tid >> 4;
    const int l16 = tid & 15;

    __shared__ float4 sh_k4[16];
    __shared__ float sh_wr[128];
    __shared__ float sh_wlu[128];
    __shared__ float sh_E[128];
    __shared__ float s_knorm;

    const float4* __restrict__ mem4 = (const float4*)memory;
    const size_t base = ((size_t)b * Nq + n0 + hw) * (Mq / 4) + l16;

    // ---- pre-sync: Phase A loads + w_prev staging (inputs only) ----
    float4 m[4];
#pragma unroll
    for (int r = 0; r < 4; r++)
        m[r] = __ldcs(&mem4[base + (size_t)r * 32 * (Mq / 4)]);

    if (tid < 128) {
        const int n = n0 + tid;
        sh_wr[tid]  = w_prev[((size_t)b * 3 + 1) * Nq + n];
        sh_wlu[tid] = w_prev[((size_t)b * 3 + 2) * Nq + n];
    }

    // ---- wait for proj outputs ----
    cudaGridDependencySynchronize();

    const float gv = g_gate[b];
    const float beta = g_beta[b];

    float kn = 0.0f;
    if (tid < 16) {
        const float4 k4 = ((const float4*)(g_k + (size_t)b * Mq))[tid];
        sh_k4[tid] = k4;
        kn = k4.x * k4.x + k4.y * k4.y + k4.z * k4.z + k4.w * k4.w;
    }
    if (tid < 32) {
#pragma unroll
        for (int s = 8; s > 0; s >>= 1)
            kn += __shfl_xor_sync(0xffffffffu, kn, s);
        if (tid == 0) s_knorm = sqrtf(kn);
    }
    __syncthreads();

    const float knorm = s_knorm;
    const float4 kv = sh_k4[l16];
    float* __restrict__ newmem = out + (size_t)Bq * 3 * Nq;
    float4* __restrict__ out4 = (float4*)newmem;

    // Phase B: all stores (independent of shuffle chains)
#pragma unroll
    for (int r = 0; r < 4; r++) {
        const int local = hw + 32 * r;
        const float ww = gv * sh_wr[local] + (1.0f - gv) * sh_wlu[local];
        float4 o4;
        o4.x = m[r].x + ww * kv.x;
        o4.y = m[r].y + ww * kv.y;
        o4.z = m[r].z + ww * kv.z;
        o4.w = m[r].w + ww * kv.w;
        __stcs(&out4[base + (size_t)r * 32 * (Mq / 4)], o4);
    }

    // Phase C: reductions -> E = exp(beta*(sim-1))
#pragma unroll
    for (int r = 0; r < 4; r++) {
        float dot = m[r].x * kv.x + m[r].y * kv.y + m[r].z * kv.z + m[r].w * kv.w;
        float nrm = m[r].x * m[r].x + m[r].y * m[r].y + m[r].z * m[r].z + m[r].w * m[r].w;
#pragma unroll
        for (int s = 8; s > 0; s >>= 1) {
            dot += __shfl_xor_sync(0xffffffffu, dot, s);
            nrm += __shfl_xor_sync(0xffffffffu, nrm, s);
        }
        if (l16 == 0) {
            const float sim = dot / (knorm * sqrtf(nrm) + EPSq);
            sh_E[hw + 32 * r] = expf(beta * (sim - 1.0f));
        }
    }
    __syncthreads();

    if (tid < 32) {
        const float4 e4 = ((const float4*)sh_E)[tid];
        ((float4*)(g_E + (size_t)b * Nq + n0))[tid] = e4;
        float ps = e4.x + e4.y + e4.z + e4.w;
#pragma unroll
        for (int s = 16; s > 0; s >>= 1)
            ps += __shfl_xor_sync(0xffffffffu, ps, s);
        if (tid == 0) g_psum[b * CHUNKS + blockIdx.x] = ps;
    }
}

// ---------------- kernel 3: elementwise + per-chunk top-4 + last-block merge ----
// grid: 256 blocks (4 per batch), 1024 threads, 4 elems/thread.
// PDL: w_prev loads + w_lu zero-fill pre-sync (overlap K2 tail); E/psum post-sync.
__global__ void __launch_bounds__(1024, 1)
ntm_elem_kernel(const float* __restrict__ w_prev, float* __restrict__ out) {
    const int blk = blockIdx.x;
    const int b = blk >> 2;
    const int c = blk & 3;
    const int tid = threadIdx.x;
    const int warp = tid >> 5;
    const int lane = tid & 31;
    const int nbase = c * 4096;

    __shared__ float s_inv;
    __shared__ unsigned long long sh_keys[128];
    __shared__ int s_last;

    const float* __restrict__ wup  = w_prev + (size_t)b * 3 * Nq;
    const float* __restrict__ wrp  = wup + Nq;
    const float* __restrict__ wlup = wup + 2 * Nq;
    float* __restrict__ w_u_out  = out + (size_t)b * 3 * Nq;
    float* __restrict__ w_r_out  = w_u_out + Nq;
    float* __restrict__ w_lu_out = w_u_out + 2 * Nq;

    // ---- pre-sync: input loads + zero-fill (independent of K2) ----
    float vu[4], vr[4], vl[4];
#pragma unroll
    for (int j = 0; j < 4; j++) {
        const int n = nbase + j * 1024 + tid;
        vu[j] = wup[n];
        vr[j] = wrp[n];
        vl[j] = wlup[n];
        w_lu_out[n] = 0.0f;
    }

    // ---- wait for K2 (E, psum, gate all visible) ----
    cudaGridDependencySynchronize();

    // reduce the 128 partial sums (deterministic fixed order)
    if (tid < 32) {
        const float* __restrict__ ps = g_psum + b * CHUNKS;
        float v = ps[tid] + ps[tid + 32] + ps[tid + 64] + ps[tid + 96];
#pragma unroll
        for (int s = 16; s > 0; s >>= 1)
            v += __shfl_xor_sync(0xffffffffu, v, s);
        if (tid == 0) s_inv = 1.0f / v;
    }
    __syncthreads();
    const float inv = s_inv;
    const float gv = g_gate[b];
    const float* __restrict__ Ep = g_E + (size_t)b * Nq;

    unsigned long long tk[4] = {~0ULL, ~0ULL, ~0ULL, ~0ULL};

#pragma unroll
    for (int j = 0; j < 4; j++) {
        const int n = nbase + j * 1024 + tid;
        const float wr = Ep[n] * inv;
        const float ww = gv * vr[j] + (1.0f - gv) * vl[j];
        const float wu = GAMMAq * vu[j] + wr + ww;
        w_r_out[n] = wr;
        w_u_out[n] = wu;

        const unsigned long long key =
            ((unsigned long long)__float_as_uint(wu) << 32) | (unsigned int)n;
        if (key < tk[3]) {
            tk[3] = key;
#pragma unroll
            for (int q = 3; q > 0; q--) {
                if (tk[q] < tk[q - 1]) {
                    unsigned long long t = tk[q]; tk[q] = tk[q - 1]; tk[q - 1] = t;
                }
            }
        }
    }

    // per-warp top-4 via 4 rounds of shfl argmin + pop (no barriers)
#pragma unroll
    for (int round = 0; round < 4; round++) {
        unsigned long long v = tk[0];
#pragma unroll
        for (int s = 16; s > 0; s >>= 1) {
            const unsigned long long o = __shfl_xor_sync(0xffffffffu, v, s);
            if (o < v) v = o;
        }
        if (tk[0] == v) {  // unique key -> exactly one popper
            tk[0] = tk[1]; tk[1] = tk[2]; tk[2] = tk[3]; tk[3] = ~0ULL;
        }
        if (lane == 0) sh_keys[warp * 4 + round] = v;
    }
    __syncthreads();

    // warp 0: reduce 128 candidates -> this chunk's top-4 -> g_cand
    if (warp == 0) {
        unsigned long long bk[4] = {~0ULL, ~0ULL, ~0ULL, ~0ULL};
#pragma unroll
        for (int j = 0; j < 4; j++) {
            const unsigned long long key = sh_keys[lane + 32 * j];
            if (key < bk[3]) {
                bk[3] = key;
#pragma unroll
                for (int q = 3; q > 0; q--) {
                    if (bk[q] < bk[q - 1]) {
                        unsigned long long t = bk[q]; bk[q] = bk[q - 1]; bk[q - 1] = t;
                    }
                }
            }
        }
#pragma unroll
        for (int round = 0; round < 4; round++) {
            unsigned long long v = bk[0];
#pragma unroll
            for (int s = 16; s > 0; s >>= 1) {
                const unsigned long long o = __shfl_xor_sync(0xffffffffu, v, s);
                if (o < v) v = o;
            }
            if (bk[0] == v) {
                bk[0] = bk[1]; bk[1] = bk[2]; bk[2] = bk[3]; bk[3] = ~0ULL;
            }
            if (lane == round) g_cand[(b * 4 + c) * 4 + round] = v;
        }
    }
    __syncthreads();

    // ticket: last block of this batch merges + scatters
    if (tid == 0) {
        __threadfence();
        s_last = (atomicAdd(&g_ticket[b], 1) == 3);
    }
    __syncthreads();

    if (s_last && warp == 0) {
        unsigned long long key = (lane < 16) ? g_cand[b * 16 + lane] : ~0ULL;
#pragma unroll
        for (int round = 0; round < 4; round++) {
            unsigned long long v = key;
#pragma unroll
            for (int s = 16; s > 0; s >>= 1) {
                const unsigned long long o = __shfl_xor_sync(0xffffffffu, v, s);
                if (o < v) v = o;
            }
            if (key == v) key = ~0ULL;  // pop winner
            if (lane == round)
                w_lu_out[(int)(unsigned int)(v & 0xffffffffu)] = 1.0f;
        }
    }
}

// ---------------- launch ----------------
extern "C" void kernel_launch(void* const* d_in, const int* in_sizes, int n_in,
                              void* d_out, int out_size) {
    const float* emb    = (const float*)d_in[0];  // (64, 256)
    const float* w_prev = (const float*)d_in[1];  // (64, 3, 16384)
    const float* memory = (const float*)d_in[2];  // (64, 16384, 64)
    const float* W      = (const float*)d_in[3];  // (66, 256)
    const float* bias   = (const float*)d_in[4];  // (66,)
    float* out = (float*)d_out;  // [w (64*3*16384) | new_memory (64*16384*64)]

    const int nwarps = Bq * NOUT;                 // 4224
    const int nblk1 = (nwarps * 32 + 255) / 256;  // 528
    ntm_proj_kernel<<<nblk1, 256>>>(emb, W, bias);

    // K2 with programmatic dependent launch (overlaps proj tail)
    {
        cudaLaunchConfig_t cfg = {};
        cfg.gridDim = dim3(CHUNKS, Bq);
        cfg.blockDim = dim3(512);
        cudaLaunchAttribute attr[1];
        attr[0].id = cudaLaunchAttributeProgrammaticStreamSerialization;
        attr[0].val.programmaticStreamSerializationAllowed = 1;
        cfg.attrs = attr;
        cfg.numAttrs = 1;
        cudaLaunchKernelEx(&cfg, ntm_stream_kernel, memory, w_prev, out);
    }

    // K3 with programmatic dependent launch (overlaps K2 tail)
    {
        cudaLaunchConfig_t cfg = {};
        cfg.gridDim = dim3(Bq * 4);
        cfg.blockDim = dim3(1024);
        cudaLaunchAttribute attr[1];
        attr[0].id = cudaLaunchAttributeProgrammaticStreamSerialization;
        attr[0].val.programmaticStreamSerializationAllowed = 1;
        cfg.attrs = attr;
        cfg.numAttrs = 1;
        cudaLaunchKernelEx(&cfg, ntm_elem_kernel, w_prev, out);
    }
}

// round 10
// speedup vs baseline: 1.5408x; 1.0212x over previous
#include <cuda_runtime.h>
#include <math.h>
#include <float.h>

#define Bq 64
#define Nq 16384
#define Mq 64
#define Cq 256
#define GAMMAq 0.95f
#define EPSq 1e-16f
#define NOUT 66     // M + 2
#define CHUNKS 128  // K2 grid.x = Nq/128

// ---------------- scratch (static device globals; no allocation) ----------------
__device__ float g_k[Bq * Mq];
__device__ float g_beta[Bq];
__device__ float g_gate[Bq];
__device__ float g_E[(size_t)Bq * Nq];           // exp(beta*(sim-1))
__device__ float g_psum[Bq * CHUNKS];            // per-K2-block partial sums of E
__device__ unsigned long long g_cand[Bq * 16];   // 4 chunks x 4 candidate keys
__device__ int g_ticket[Bq];                     // last-block-done tickets

// ---------------- kernel 1: projection, warp per (batch, output) ----------------
__global__ void ntm_proj_kernel(const float* __restrict__ emb,
                                const float* __restrict__ W,
                                const float* __restrict__ bias) {
    if (blockIdx.x == 0 && threadIdx.x < Bq) g_ticket[threadIdx.x] = 0;

    const int wglob = (blockIdx.x * blockDim.x + threadIdx.x) >> 5;
    const int lane = threadIdx.x & 31;
    if (wglob < Bq * NOUT) {
        const int b = wglob / NOUT;
        const int o = wglob - b * NOUT;

        const float* __restrict__ e = emb + (size_t)b * Cq;
        const float* __restrict__ w = W + (size_t)o * Cq;

        float acc = 0.0f;
#pragma unroll
        for (int i = 0; i < 8; i++) {
            const int c = lane + 32 * i;
            acc = fmaf(__ldg(&e[c]), __ldg(&w[c]), acc);
        }
#pragma unroll
        for (int s = 16; s > 0; s >>= 1)
            acc += __shfl_xor_sync(0xffffffffu, acc, s);

        if (lane == 0) {
            acc += bias[o];
            if (o < Mq) {
                g_k[b * Mq + o] = acc;
            } else if (o == Mq) {
                g_beta[b] = (acc > 20.0f) ? acc : log1pf(expf(acc));
            } else {
                g_gate[b] = 1.0f / (1.0f + expf(-acc));
            }
        }
    }
    // all writes for this block are done -> let K2 blocks launch/run
    cudaTriggerProgrammaticLaunchCompletion();
}

// ---------------- kernel 2: fused sim/exp + new_memory streaming pass -----------
// grid: (CHUNKS, Bq), block 512, >=3 blocks/SM. Phase A/B/C structure.
__global__ void __launch_bounds__(512, 3)
ntm_stream_kernel(const float* __restrict__ memory,
                  const float* __restrict__ w_prev,
                  float* __restrict__ out) {
    const int b = blockIdx.y;
    const int n0 = blockIdx.x * 128;
    const int tid = threadIdx.x;
    const int hw = tid >> 4;
    const int l16 = tid & 15;

    __shared__ float4 sh_k4[16];
    __shared__ float sh_wr[128];
    __shared__ float sh_wlu[128];
    __shared__ float sh_E[128];
    __shared__ float s_knorm;

    const float4* __restrict__ mem4 = (const float4*)memory;
    const size_t base = ((size_t)b * Nq + n0 + hw) * (Mq / 4) + l16;

    // ---- pre-sync: Phase A loads + w_prev staging (pure inputs) ----
    float4 m[4];
#pragma unroll
    for (int r = 0; r < 4; r++)
        m[r] = __ldcs(&mem4[base + (size_t)r * 32 * (Mq / 4)]);

    if (tid < 128) {
        const int n = n0 + tid;
        sh_wr[tid]  = w_prev[((size_t)b * 3 + 1) * Nq + n];
        sh_wlu[tid] = w_prev[((size_t)b * 3 + 2) * Nq + n];
    }

    // ---- wait for proj outputs ----
    cudaGridDependencySynchronize();

    const float gv = g_gate[b];
    const float beta = g_beta[b];

    float kn = 0.0f;
    if (tid < 16) {
        const float4 k4 = ((const float4*)(g_k + (size_t)b * Mq))[tid];
        sh_k4[tid] = k4;
        kn = k4.x * k4.x + k4.y * k4.y + k4.z * k4.z + k4.w * k4.w;
    }
    if (tid < 32) {
#pragma unroll
        for (int s = 8; s > 0; s >>= 1)
            kn += __shfl_xor_sync(0xffffffffu, kn, s);
        if (tid == 0) s_knorm = sqrtf(kn);
    }
    __syncthreads();

    const float knorm = s_knorm;
    const float4 kv = sh_k4[l16];
    float* __restrict__ newmem = out + (size_t)Bq * 3 * Nq;
    float4* __restrict__ out4 = (float4*)newmem;

    // Phase B: all stores (independent of shuffle chains)
#pragma unroll
    for (int r = 0; r < 4; r++) {
        const int local = hw + 32 * r;
        const float ww = gv * sh_wr[local] + (1.0f - gv) * sh_wlu[local];
        float4 o4;
        o4.x = m[r].x + ww * kv.x;
        o4.y = m[r].y + ww * kv.y;
        o4.z = m[r].z + ww * kv.z;
        o4.w = m[r].w + ww * kv.w;
        __stcs(&out4[base + (size_t)r * 32 * (Mq / 4)], o4);
    }

    // Phase C: reductions -> E = exp(beta*(sim-1))
#pragma unroll
    for (int r = 0; r < 4; r++) {
        float dot = m[r].x * kv.x + m[r].y * kv.y + m[r].z * kv.z + m[r].w * kv.w;
        float nrm = m[r].x * m[r].x + m[r].y * m[r].y + m[r].z * m[r].z + m[r].w * m[r].w;
#pragma unroll
        for (int s = 8; s > 0; s >>= 1) {
            dot += __shfl_xor_sync(0xffffffffu, dot, s);
            nrm += __shfl_xor_sync(0xffffffffu, nrm, s);
        }
        if (l16 == 0) {
            const float sim = dot / (knorm * sqrtf(nrm) + EPSq);
            sh_E[hw + 32 * r] = expf(beta * (sim - 1.0f));
        }
    }
    __syncthreads();

    if (tid < 32) {
        const float4 e4 = ((const float4*)sh_E)[tid];
        ((float4*)(g_E + (size_t)b * Nq + n0))[tid] = e4;
        float ps = e4.x + e4.y + e4.z + e4.w;
#pragma unroll
        for (int s = 16; s > 0; s >>= 1)
            ps += __shfl_xor_sync(0xffffffffu, ps, s);
        if (tid == 0) g_psum[b * CHUNKS + blockIdx.x] = ps;
    }
    // all writes (new_memory, E, psum) issued for this block -> signal
    cudaTriggerProgrammaticLaunchCompletion();
}

// ---------------- kernel 3: elementwise + per-chunk top-4 + last-block merge ----
// grid: 256 blocks (4 per batch), 1024 threads, 4 elems/thread.
// PDL: w_prev loads + w_lu zero-fill pre-sync (overlap K2 tail); E/psum post-sync.
__global__ void __launch_bounds__(1024, 1)
ntm_elem_kernel(const float* __restrict__ w_prev, float* __restrict__ out) {
    const int blk = blockIdx.x;
    const int b = blk >> 2;
    const int c = blk & 3;
    const int tid = threadIdx.x;
    const int warp = tid >> 5;
    const int lane = tid & 31;
    const int nbase = c * 4096;

    __shared__ float s_inv;
    __shared__ unsigned long long sh_keys[128];
    __shared__ int s_last;

    const float* __restrict__ wup  = w_prev + (size_t)b * 3 * Nq;
    const float* __restrict__ wrp  = wup + Nq;
    const float* __restrict__ wlup = wup + 2 * Nq;
    float* __restrict__ w_u_out  = out + (size_t)b * 3 * Nq;
    float* __restrict__ w_r_out  = w_u_out + Nq;
    float* __restrict__ w_lu_out = w_u_out + 2 * Nq;

    // ---- pre-sync: input loads + zero-fill (independent of K2) ----
    float vu[4], vr[4], vl[4];
#pragma unroll
    for (int j = 0; j < 4; j++) {
        const int n = nbase + j * 1024 + tid;
        vu[j] = wup[n];
        vr[j] = wrp[n];
        vl[j] = wlup[n];
        w_lu_out[n] = 0.0f;
    }

    // ---- wait for K2 (E, psum, gate all visible) ----
    cudaGridDependencySynchronize();

    // reduce the 128 partial sums (deterministic fixed order)
    if (tid < 32) {
        const float* __restrict__ ps = g_psum + b * CHUNKS;
        float v = ps[tid] + ps[tid + 32] + ps[tid + 64] + ps[tid + 96];
#pragma unroll
        for (int s = 16; s > 0; s >>= 1)
            v += __shfl_xor_sync(0xffffffffu, v, s);
        if (tid == 0) s_inv = 1.0f / v;
    }
    __syncthreads();
    const float inv = s_inv;
    const float gv = g_gate[b];
    const float* __restrict__ Ep = g_E + (size_t)b * Nq;

    unsigned long long tk[4] = {~0ULL, ~0ULL, ~0ULL, ~0ULL};

#pragma unroll
    for (int j = 0; j < 4; j++) {
        const int n = nbase + j * 1024 + tid;
        const float wr = Ep[n] * inv;
        const float ww = gv * vr[j] + (1.0f - gv) * vl[j];
        const float wu = GAMMAq * vu[j] + wr + ww;
        w_r_out[n] = wr;
        w_u_out[n] = wu;

        const unsigned long long key =
            ((unsigned long long)__float_as_uint(wu) << 32) | (unsigned int)n;
        if (key < tk[3]) {
            tk[3] = key;
#pragma unroll
            for (int q = 3; q > 0; q--) {
                if (tk[q] < tk[q - 1]) {
                    unsigned long long t = tk[q]; tk[q] = tk[q - 1]; tk[q - 1] = t;
                }
            }
        }
    }

    // per-warp top-4 via 4 rounds of shfl argmin + pop (no barriers)
#pragma unroll
    for (int round = 0; round < 4; round++) {
        unsigned long long v = tk[0];
#pragma unroll
        for (int s = 16; s > 0; s >>= 1) {
            const unsigned long long o = __shfl_xor_sync(0xffffffffu, v, s);
            if (o < v) v = o;
        }
        if (tk[0] == v) {  // unique key -> exactly one popper
            tk[0] = tk[1]; tk[1] = tk[2]; tk[2] = tk[3]; tk[3] = ~0ULL;
        }
        if (lane == 0) sh_keys[warp * 4 + round] = v;
    }
    __syncthreads();

    // warp 0: reduce 128 candidates -> this chunk's top-4 -> g_cand
    if (warp == 0) {
        unsigned long long bk[4] = {~0ULL, ~0ULL, ~0ULL, ~0ULL};
#pragma unroll
        for (int j = 0; j < 4; j++) {
            const unsigned long long key = sh_keys[lane + 32 * j];
            if (key < bk[3]) {
                bk[3] = key;
#pragma unroll
                for (int q = 3; q > 0; q--) {
                    if (bk[q] < bk[q - 1]) {
                        unsigned long long t = bk[q]; bk[q] = bk[q - 1]; bk[q - 1] = t;
                    }
                }
            }
        }
#pragma unroll
        for (int round = 0; round < 4; round++) {
            unsigned long long v = bk[0];
#pragma unroll
            for (int s = 16; s > 0; s >>= 1) {
                const unsigned long long o = __shfl_xor_sync(0xffffffffu, v, s);
                if (o < v) v = o;
            }
            if (bk[0] == v) {
                bk[0] = bk[1]; bk[1] = bk[2]; bk[2] = bk[3]; bk[3] = ~0ULL;
            }
            if (lane == round) g_cand[(b * 4 + c) * 4 + round] = v;
        }
    }
    __syncthreads();

    // ticket: last block of this batch merges + scatters
    if (tid == 0) {
        __threadfence();
        s_last = (atomicAdd(&g_ticket[b], 1) == 3);
    }
    __syncthreads();

    if (s_last && warp == 0) {
        unsigned long long key = (lane < 16) ? g_cand[b * 16 + lane] : ~0ULL;
#pragma unroll
        for (int round = 0; round < 4; round++) {
            unsigned long long v = key;
#pragma unroll
            for (int s = 16; s > 0; s >>= 1) {
                const unsigned long long o = __shfl_xor_sync(0xffffffffu, v, s);
                if (o < v) v = o;
            }
            if (key == v) key = ~0ULL;  // pop winner
            if (lane == round)
                w_lu_out[(int)(unsigned int)(v & 0xffffffffu)] = 1.0f;
        }
    }
}

// ---------------- launch ----------------
extern "C" void kernel_launch(void* const* d_in, const int* in_sizes, int n_in,
                              void* d_out, int out_size) {
    const float* emb    = (const float*)d_in[0];  // (64, 256)
    const float* w_prev = (const float*)d_in[1];  // (64, 3, 16384)
    const float* memory = (const float*)d_in[2];  // (64, 16384, 64)
    const float* W      = (const float*)d_in[3];  // (66, 256)
    const float* bias   = (const float*)d_in[4];  // (66,)
    float* out = (float*)d_out;  // [w (64*3*16384) | new_memory (64*16384*64)]

    const int nwarps = Bq * NOUT;                 // 4224
    const int nblk1 = (nwarps * 32 + 255) / 256;  // 528
    ntm_proj_kernel<<<nblk1, 256>>>(emb, W, bias);

    // K2: PDL secondary of proj
    {
        cudaLaunchConfig_t cfg = {};
        cfg.gridDim = dim3(CHUNKS, Bq);
        cfg.blockDim = dim3(512);
        cudaLaunchAttribute attr[1];
        attr[0].id = cudaLaunchAttributeProgrammaticStreamSerialization;
        attr[0].val.programmaticStreamSerializationAllowed = 1;
        cfg.attrs = attr;
        cfg.numAttrs = 1;
        cudaLaunchKernelEx(&cfg, ntm_stream_kernel, memory, w_prev, out);
    }

    // K3: PDL secondary of K2
    {
        cudaLaunchConfig_t cfg = {};
        cfg.gridDim = dim3(Bq * 4);
        cfg.blockDim = dim3(1024);
        cudaLaunchAttribute attr[1];
        attr[0].id = cudaLaunchAttributeProgrammaticStreamSerialization;
        attr[0].val.programmaticStreamSerializationAllowed = 1;
        cfg.attrs = attr;
        cfg.numAttrs = 1;
        cudaLaunchKernelEx(&cfg, ntm_elem_kernel, w_prev, out);
    }
}

// round 11
// speedup vs baseline: 1.5689x; 1.0182x over previous
#include <cuda_runtime.h>
#include <math.h>
#include <float.h>

#define Bq 64
#define Nq 16384
#define Mq 64
#define Cq 256
#define GAMMAq 0.95f
#define EPSq 1e-16f
#define NOUT 66     // M + 2
#define CHUNKS 128  // K2 grid.x = Nq/128

// ---------------- scratch (static device globals; no allocation) ----------------
__device__ float g_k[Bq * Mq];
__device__ float g_beta[Bq];
__device__ float g_gate[Bq];
__device__ float g_E[(size_t)Bq * Nq];           // exp(beta*(sim-1))
__device__ float g_psum[Bq * CHUNKS];            // per-K2-block partial sums of E
__device__ unsigned long long g_cand[Bq * 16];   // 4 chunks x 4 candidate keys
__device__ int g_ticket[Bq];                     // last-block-done tickets

// ---------------- kernel 1: projection, warp per (batch, output) ----------------
__global__ void ntm_proj_kernel(const float* __restrict__ emb,
                                const float* __restrict__ W,
                                const float* __restrict__ bias) {
    if (blockIdx.x == 0 && threadIdx.x < Bq) g_ticket[threadIdx.x] = 0;

    const int wglob = (blockIdx.x * blockDim.x + threadIdx.x) >> 5;
    const int lane = threadIdx.x & 31;
    if (wglob < Bq * NOUT) {
        const int b = wglob / NOUT;
        const int o = wglob - b * NOUT;

        const float* __restrict__ e = emb + (size_t)b * Cq;
        const float* __restrict__ w = W + (size_t)o * Cq;

        float acc = 0.0f;
#pragma unroll
        for (int i = 0; i < 8; i++) {
            const int c = lane + 32 * i;
            acc = fmaf(__ldg(&e[c]), __ldg(&w[c]), acc);
        }
#pragma unroll
        for (int s = 16; s > 0; s >>= 1)
            acc += __shfl_xor_sync(0xffffffffu, acc, s);

        if (lane == 0) {
            acc += bias[o];
            if (o < Mq) {
                g_k[b * Mq + o] = acc;
            } else if (o == Mq) {
                g_beta[b] = (acc > 20.0f) ? acc : log1pf(expf(acc));
            } else {
                g_gate[b] = 1.0f / (1.0f + expf(-acc));
            }
        }
    }
    cudaTriggerProgrammaticLaunchCompletion();
}

// ---------------- kernel 2: fused sim/exp + new_memory streaming pass -----------
// grid: (CHUNKS, Bq), block 512, >=3 blocks/SM. Phase A/B/C structure.
__global__ void __launch_bounds__(512, 3)
ntm_stream_kernel(const float* __restrict__ memory,
                  const float* __restrict__ w_prev,
                  float* __restrict__ out) {
    const int b = blockIdx.y;
    const int n0 = blockIdx.x * 128;
    const int tid = threadIdx.x;
    const int hw = tid >> 4;
    const int l16 = tid & 15;

    __shared__ float4 sh_k4[16];
    __shared__ float sh_wr[128];
    __shared__ float sh_wlu[128];
    __shared__ float sh_E[128];
    __shared__ float s_knorm;

    const float4* __restrict__ mem4 = (const float4*)memory;
    const size_t base = ((size_t)b * Nq + n0 + hw) * (Mq / 4) + l16;

    // ---- pre-sync: Phase A loads + w_prev staging (pure inputs) ----
    float4 m[4];
#pragma unroll
    for (int r = 0; r < 4; r++)
        m[r] = __ldcs(&mem4[base + (size_t)r * 32 * (Mq / 4)]);

    if (tid < 128) {
        const int n = n0 + tid;
        sh_wr[tid]  = w_prev[((size_t)b * 3 + 1) * Nq + n];
        sh_wlu[tid] = w_prev[((size_t)b * 3 + 2) * Nq + n];
    }

    // ---- wait for proj outputs ----
    cudaGridDependencySynchronize();

    const float gv = g_gate[b];
    const float beta = g_beta[b];

    float kn = 0.0f;
    if (tid < 16) {
        const float4 k4 = ((const float4*)(g_k + (size_t)b * Mq))[tid];
        sh_k4[tid] = k4;
        kn = k4.x * k4.x + k4.y * k4.y + k4.z * k4.z + k4.w * k4.w;
    }
    if (tid < 32) {
#pragma unroll
        for (int s = 8; s > 0; s >>= 1)
            kn += __shfl_xor_sync(0xffffffffu, kn, s);
        if (tid == 0) s_knorm = sqrtf(kn);
    }
    __syncthreads();

    const float knorm = s_knorm;
    const float4 kv = sh_k4[l16];
    float* __restrict__ newmem = out + (size_t)Bq * 3 * Nq;
    float4* __restrict__ out4 = (float4*)newmem;

    // Phase B: all stores (independent of shuffle chains)
#pragma unroll
    for (int r = 0; r < 4; r++) {
        const int local = hw + 32 * r;
        const float ww = gv * sh_wr[local] + (1.0f - gv) * sh_wlu[local];
        float4 o4;
        o4.x = m[r].x + ww * kv.x;
        o4.y = m[r].y + ww * kv.y;
        o4.z = m[r].z + ww * kv.z;
        o4.w = m[r].w + ww * kv.w;
        __stcs(&out4[base + (size_t)r * 32 * (Mq / 4)], o4);
    }

    // Phase C: reductions -> E = exp(beta*(sim-1))
#pragma unroll
    for (int r = 0; r < 4; r++) {
        float dot = m[r].x * kv.x + m[r].y * kv.y + m[r].z * kv.z + m[r].w * kv.w;
        float nrm = m[r].x * m[r].x + m[r].y * m[r].y + m[r].z * m[r].z + m[r].w * m[r].w;
#pragma unroll
        for (int s = 8; s > 0; s >>= 1) {
            dot += __shfl_xor_sync(0xffffffffu, dot, s);
            nrm += __shfl_xor_sync(0xffffffffu, nrm, s);
        }
        if (l16 == 0) {
            const float sim = dot / (knorm * sqrtf(nrm) + EPSq);
            sh_E[hw + 32 * r] = expf(beta * (sim - 1.0f));
        }
    }
    __syncthreads();

    if (tid < 32) {
        const float4 e4 = ((const float4*)sh_E)[tid];
        ((float4*)(g_E + (size_t)b * Nq + n0))[tid] = e4;
        float ps = e4.x + e4.y + e4.z + e4.w;
#pragma unroll
        for (int s = 16; s > 0; s >>= 1)
            ps += __shfl_xor_sync(0xffffffffu, ps, s);
        if (tid == 0) g_psum[b * CHUNKS + blockIdx.x] = ps;
    }
    cudaTriggerProgrammaticLaunchCompletion();
}

// ---------------- kernel 3: elementwise (float4) + top-4 + last-block merge -----
// grid: 256 blocks (4 per batch), 1024 threads, 4 CONSECUTIVE elems/thread.
// All loads/stores are 128-bit; top-4 keys remain exact (unique index tiebreak).
__global__ void __launch_bounds__(1024, 1)
ntm_elem_kernel(const float* __restrict__ w_prev, float* __restrict__ out) {
    const int blk = blockIdx.x;
    const int b = blk >> 2;
    const int c = blk & 3;
    const int tid = threadIdx.x;
    const int warp = tid >> 5;
    const int lane = tid & 31;
    const int n = c * 4096 + tid * 4;   // 4 consecutive elements per thread

    __shared__ float s_inv;
    __shared__ unsigned long long sh_keys[128];
    __shared__ int s_last;

    const float* __restrict__ wup  = w_prev + (size_t)b * 3 * Nq;
    const float* __restrict__ wrp  = wup + Nq;
    const float* __restrict__ wlup = wup + 2 * Nq;
    float* __restrict__ w_u_out  = out + (size_t)b * 3 * Nq;
    float* __restrict__ w_r_out  = w_u_out + Nq;
    float* __restrict__ w_lu_out = w_u_out + 2 * Nq;

    // ---- pre-sync: vectorized input loads + zero-fill (independent of K2) ----
    const float4 vu = *(const float4*)(wup + n);
    const float4 vr = *(const float4*)(wrp + n);
    const float4 vl = *(const float4*)(wlup + n);
    __stcs((float4*)(w_lu_out + n), make_float4(0.f, 0.f, 0.f, 0.f));

    // ---- wait for K2 (E, psum, gate all visible) ----
    cudaGridDependencySynchronize();

    // reduce the 128 partial sums (deterministic fixed order)
    if (tid < 32) {
        const float* __restrict__ ps = g_psum + b * CHUNKS;
        float v = ps[tid] + ps[tid + 32] + ps[tid + 64] + ps[tid + 96];
#pragma unroll
        for (int s = 16; s > 0; s >>= 1)
            v += __shfl_xor_sync(0xffffffffu, v, s);
        if (tid == 0) s_inv = 1.0f / v;
    }
    __syncthreads();
    const float inv = s_inv;
    const float gv = g_gate[b];

    const float4 e4 = *(const float4*)(g_E + (size_t)b * Nq + n);

    float4 wr4, wu4;
    wr4.x = e4.x * inv;  wr4.y = e4.y * inv;  wr4.z = e4.z * inv;  wr4.w = e4.w * inv;
    wu4.x = GAMMAq * vu.x + wr4.x + (gv * vr.x + (1.0f - gv) * vl.x);
    wu4.y = GAMMAq * vu.y + wr4.y + (gv * vr.y + (1.0f - gv) * vl.y);
    wu4.z = GAMMAq * vu.z + wr4.z + (gv * vr.z + (1.0f - gv) * vl.z);
    wu4.w = GAMMAq * vu.w + wr4.w + (gv * vr.w + (1.0f - gv) * vl.w);

    __stcs((float4*)(w_r_out + n), wr4);
    __stcs((float4*)(w_u_out + n), wu4);

    // thread-local top-4 over its 4 values (packed keys; wu > 0)
    unsigned long long tk[4] = {~0ULL, ~0ULL, ~0ULL, ~0ULL};
    const float wvals[4] = {wu4.x, wu4.y, wu4.z, wu4.w};
#pragma unroll
    for (int j = 0; j < 4; j++) {
        const unsigned long long key =
            ((unsigned long long)__float_as_uint(wvals[j]) << 32) | (unsigned int)(n + j);
        if (key < tk[3]) {
            tk[3] = key;
#pragma unroll
            for (int q = 3; q > 0; q--) {
                if (tk[q] < tk[q - 1]) {
                    unsigned long long t = tk[q]; tk[q] = tk[q - 1]; tk[q - 1] = t;
                }
            }
        }
    }

    // per-warp top-4 via 4 rounds of shfl argmin + pop (no barriers)
#pragma unroll
    for (int round = 0; round < 4; round++) {
        unsigned long long v = tk[0];
#pragma unroll
        for (int s = 16; s > 0; s >>= 1) {
            const unsigned long long o = __shfl_xor_sync(0xffffffffu, v, s);
            if (o < v) v = o;
        }
        if (tk[0] == v) {  // unique key -> exactly one popper
            tk[0] = tk[1]; tk[1] = tk[2]; tk[2] = tk[3]; tk[3] = ~0ULL;
        }
        if (lane == 0) sh_keys[warp * 4 + round] = v;
    }
    __syncthreads();

    // warp 0: reduce 128 candidates -> this chunk's top-4 -> g_cand
    if (warp == 0) {
        unsigned long long bk[4] = {~0ULL, ~0ULL, ~0ULL, ~0ULL};
#pragma unroll
        for (int j = 0; j < 4; j++) {
            const unsigned long long key = sh_keys[lane + 32 * j];
            if (key < bk[3]) {
                bk[3] = key;
#pragma unroll
                for (int q = 3; q > 0; q--) {
                    if (bk[q] < bk[q - 1]) {
                        unsigned long long t = bk[q]; bk[q] = bk[q - 1]; bk[q - 1] = t;
                    }
                }
            }
        }
#pragma unroll
        for (int round = 0; round < 4; round++) {
            unsigned long long v = bk[0];
#pragma unroll
            for (int s = 16; s > 0; s >>= 1) {
                const unsigned long long o = __shfl_xor_sync(0xffffffffu, v, s);
                if (o < v) v = o;
            }
            if (bk[0] == v) {
                bk[0] = bk[1]; bk[1] = bk[2]; bk[2] = bk[3]; bk[3] = ~0ULL;
            }
            if (lane == round) g_cand[(b * 4 + c) * 4 + round] = v;
        }
    }
    __syncthreads();

    // ticket: last block of this batch merges + scatters
    if (tid == 0) {
        __threadfence();
        s_last = (atomicAdd(&g_ticket[b], 1) == 3);
    }
    __syncthreads();

    if (s_last && warp == 0) {
        unsigned long long key = (lane < 16) ? g_cand[b * 16 + lane] : ~0ULL;
#pragma unroll
        for (int round = 0; round < 4; round++) {
            unsigned long long v = key;
#pragma unroll
            for (int s = 16; s > 0; s >>= 1) {
                const unsigned long long o = __shfl_xor_sync(0xffffffffu, v, s);
                if (o < v) v = o;
            }
            if (key == v) key = ~0ULL;  // pop winner
            if (lane == round)
                w_lu_out[(int)(unsigned int)(v & 0xffffffffu)] = 1.0f;
        }
    }
}

// ---------------- launch ----------------
extern "C" void kernel_launch(void* const* d_in, const int* in_sizes, int n_in,
                              void* d_out, int out_size) {
    const float* emb    = (const float*)d_in[0];  // (64, 256)
    const float* w_prev = (const float*)d_in[1];  // (64, 3, 16384)
    const float* memory = (const float*)d_in[2];  // (64, 16384, 64)
    const float* W      = (const float*)d_in[3];  // (66, 256)
    const float* bias   = (const float*)d_in[4];  // (66,)
    float* out = (float*)d_out;  // [w (64*3*16384) | new_memory (64*16384*64)]

    const int nwarps = Bq * NOUT;                 // 4224
    const int nblk1 = (nwarps * 32 + 255) / 256;  // 528
    ntm_proj_kernel<<<nblk1, 256>>>(emb, W, bias);

    // K2: PDL secondary of proj
    {
        cudaLaunchConfig_t cfg = {};
        cfg.gridDim = dim3(CHUNKS, Bq);
        cfg.blockDim = dim3(512);
        cudaLaunchAttribute attr[1];
        attr[0].id = cudaLaunchAttributeProgrammaticStreamSerialization;
        attr[0].val.programmaticStreamSerializationAllowed = 1;
        cfg.attrs = attr;
        cfg.numAttrs = 1;
        cudaLaunchKernelEx(&cfg, ntm_stream_kernel, memory, w_prev, out);
    }

    // K3: PDL secondary of K2
    {
        cudaLaunchConfig_t cfg = {};
        cfg.gridDim = dim3(Bq * 4);
        cfg.blockDim = dim3(1024);
        cudaLaunchAttribute attr[1];
        attr[0].id = cudaLaunchAttributeProgrammaticStreamSerialization;
        attr[0].val.programmaticStreamSerializationAllowed = 1;
        cfg.attrs = attr;
        cfg.numAttrs = 1;
        cudaLaunchKernelEx(&cfg, ntm_elem_kernel, w_prev, out);
    }
}